// round 7
// baseline (speedup 1.0000x reference)
#include <cuda_runtime.h>
#include <cstdint>

// ---------------- problem constants ----------------
#define BATCH   32
#define HH      56
#define WW      56
#define CC      256
#define HEADS   8
#define HD      32
#define WIN     7
#define SHIFT   3
#define NN      49
#define NWIN    64
#define NWTOT   (BATCH * NWIN)      // 2048
#define MTOT    (NWTOT * NN)        // 100352

// ---------------- scratch (device globals; device-code refs only) ----------------
__device__ float g_qkv[(size_t)MTOT * 768];
__device__ float g_att[(size_t)MTOT * 256];
__device__ float g_bias[4 * HEADS * NN * 52];

typedef unsigned long long ull;

#define FMA2(acc, a, b) \
    asm("fma.rn.f32x2 %0, %1, %2, %0;" : "+l"(acc) : "l"(a), "l"(b))
#define UNPACK2(lo, hi, p) \
    asm("mov.b64 {%0, %1}, %2;" : "=f"(lo), "=f"(hi) : "l"(p))

// Map a flattened window-row index m -> element offset of the source pixel in x.
// roll(+3) inverts roll(-3): same map serves gather (QKV) and scatter (proj).
__device__ __forceinline__ int src_offset(int m) {
    int wq = m / NN;
    int n  = m - wq * NN;
    int b  = wq >> 6;
    int wi = wq & 63;
    int wh = wi >> 3, ww = wi & 7;
    int r = wh * WIN + n / WIN;
    int c = ww * WIN + n % WIN;
    int sh = r + SHIFT; if (sh >= HH) sh -= HH;
    int sw = c + SHIFT; if (sw >= WW) sw -= WW;
    return ((b * HH + sh) * WW + sw) * CC;
}

// =====================================================================
// Kernel 0: fused bias+mask table. 4 classes x 8 heads.
// =====================================================================
__global__ void bias_kernel(const float* __restrict__ tbl,
                            const int* __restrict__ relidx) {
    const int cls = blockIdx.x & 3;
    const int h   = blockIdx.x >> 2;
    for (int idx = threadIdx.x; idx < NN * NN; idx += blockDim.x) {
        int i = idx / NN, j = idx % NN;
        float b = tbl[relidx[idx] * HEADS + h];
        int rhi = (cls & 2) ? ((i / 7 < 4) ? 1 : 2) : 0;
        int rwi = (cls & 1) ? ((i % 7 < 4) ? 1 : 2) : 0;
        int rhj = (cls & 2) ? ((j / 7 < 4) ? 1 : 2) : 0;
        int rwj = (cls & 1) ? ((j % 7 < 4) ? 1 : 2) : 0;
        float msk = ((rhi * 3 + rwi) == (rhj * 3 + rwj)) ? 0.f : -100.f;
        g_bias[((cls * HEADS + h) * NN + i) * 52 + j] = b + msk;
    }
}

// =====================================================================
// 128x128x16 SGEMM via packed FFMA2 (fma.rn.f32x2).
//   A stored DUPLICATED in smem ((a,a) pairs) -> dup pairs come free from LDS.128
//   B pairs come free from LDS.128 reinterpret.
//   Per k-step: 6 LDS.128 + 32 FFMA2 (vs 4 LDS + 64 FFMA before).
//   QKV=true : A = X (gathered rows), C = g_qkv (ldc=768)
//   QKV=false: A = g_att (linear),    C = OUT (scattered)
// Dynamic smem: As2 [2][16][260] dup'd + Bs [2][16][132] = 50176 B
// =====================================================================
#define AS2_STRIDE 260
#define BS_STRIDE  132
#define GM_SMEM ((2 * 16 * AS2_STRIDE + 2 * 16 * BS_STRIDE) * 4)

template<bool QKV>
__global__ __launch_bounds__(256, 2) void gemm128(const float* __restrict__ X,
                                                  const float* __restrict__ W,
                                                  const float* __restrict__ bias,
                                                  float* __restrict__ OUT) {
    extern __shared__ float dsm[];
    float (*As2)[AS2_STRIDE] = (float(*)[AS2_STRIDE])dsm;                  // [32][260]
    float (*Bs)[BS_STRIDE]   = (float(*)[BS_STRIDE])(dsm + 2 * 16 * AS2_STRIDE);
    __shared__ int so[128];

    const int n0 = blockIdx.x * 128;
    const int m0 = blockIdx.y * 128;
    const int t  = threadIdx.x;

    if (t < 128) so[t] = src_offset(m0 + t);
    __syncthreads();

    // ---- load mapping ----
    const int r  = t >> 2;            // 0..63
    const int kq = t & 3;             // 0..3

    const float* ap0;
    const float* ap1;
    if (QKV) {
        ap0 = X + so[r]      + kq * 4;
        ap1 = X + so[r + 64] + kq * 4;
    } else {
        ap0 = g_att + (size_t)(m0 + r)      * 256 + kq * 4;
        ap1 = g_att + (size_t)(m0 + r + 64) * 256 + kq * 4;
    }
    const float* bp0 = W + (size_t)(n0 + r)      * CC + kq * 4;
    const float* bp1 = W + (size_t)(n0 + r + 64) * CC + kq * 4;

    // ---- compute mapping: split microtile (conflict-free) ----
    const int tx4 = (t & 15) * 4;
    const int ty4 = (t >> 4) * 4;

    ull acc[8][4];
#pragma unroll
    for (int i = 0; i < 8; i++)
#pragma unroll
        for (int j = 0; j < 4; j++) acc[i][j] = 0ull;

    // ---- prologue ----
    float4 ra0 = *(const float4*)ap0;
    float4 ra1 = *(const float4*)ap1;
    float4 rb0 = *(const float4*)bp0;
    float4 rb1 = *(const float4*)bp1;

    int buf = 0;
    {
        float a0[4] = {ra0.x, ra0.y, ra0.z, ra0.w};
        float a1[4] = {ra1.x, ra1.y, ra1.z, ra1.w};
        float b0[4] = {rb0.x, rb0.y, rb0.z, rb0.w};
        float b1[4] = {rb1.x, rb1.y, rb1.z, rb1.w};
#pragma unroll
        for (int j = 0; j < 4; j++) {
            const int kk = kq * 4 + j;
            *(float2*)&As2[kk][2 * r]        = make_float2(a0[j], a0[j]);
            *(float2*)&As2[kk][2 * (r + 64)] = make_float2(a1[j], a1[j]);
            Bs[kk][r]      = b0[j];
            Bs[kk][r + 64] = b1[j];
        }
    }
    __syncthreads();

#pragma unroll 1
    for (int it = 0; it < 16; ++it) {
        if (it < 15) {
            const int k0 = (it + 1) * 16;
            ra0 = *(const float4*)(ap0 + k0);
            ra1 = *(const float4*)(ap1 + k0);
            rb0 = *(const float4*)(bp0 + k0);
            rb1 = *(const float4*)(bp1 + k0);
        }

#pragma unroll
        for (int k = 0; k < 16; k++) {
            const int kk = buf * 16 + k;
            // B pairs: 2x LDS.128 -> 4 b64 pairs (cols tx4..+3, 64+tx4..+3)
            ulonglong2 bq0 = *(const ulonglong2*)&Bs[kk][tx4];
            ulonglong2 bq1 = *(const ulonglong2*)&Bs[kk][tx4 + 64];
            // A dup pairs: 4x LDS.128 (broadcast) -> 8 b64 (rows ty4..+3, 64+ty4..+3)
            ulonglong2 aq0 = *(const ulonglong2*)&As2[kk][2 * ty4];
            ulonglong2 aq1 = *(const ulonglong2*)&As2[kk][2 * ty4 + 4];
            ulonglong2 aq2 = *(const ulonglong2*)&As2[kk][2 * (ty4 + 64)];
            ulonglong2 aq3 = *(const ulonglong2*)&As2[kk][2 * (ty4 + 64) + 4];
            ull aa[8] = {aq0.x, aq0.y, aq1.x, aq1.y, aq2.x, aq2.y, aq3.x, aq3.y};
            ull bb[4] = {bq0.x, bq0.y, bq1.x, bq1.y};
#pragma unroll
            for (int i = 0; i < 8; i++) {
                FMA2(acc[i][0], aa[i], bb[0]);
                FMA2(acc[i][1], aa[i], bb[1]);
                FMA2(acc[i][2], aa[i], bb[2]);
                FMA2(acc[i][3], aa[i], bb[3]);
            }
        }

        if (it < 15) {
            const int nb = buf ^ 1;
            float a0[4] = {ra0.x, ra0.y, ra0.z, ra0.w};
            float a1[4] = {ra1.x, ra1.y, ra1.z, ra1.w};
            float b0[4] = {rb0.x, rb0.y, rb0.z, rb0.w};
            float b1[4] = {rb1.x, rb1.y, rb1.z, rb1.w};
#pragma unroll
            for (int j = 0; j < 4; j++) {
                const int kk = nb * 16 + kq * 4 + j;
                *(float2*)&As2[kk][2 * r]        = make_float2(a0[j], a0[j]);
                *(float2*)&As2[kk][2 * (r + 64)] = make_float2(a1[j], a1[j]);
                Bs[kk][r]      = b0[j];
                Bs[kk][r + 64] = b1[j];
            }
            __syncthreads();
            buf = nb;
        }
    }

    // ---- epilogue: rows {m0+ty4+i, m0+64+ty4+i}, cols {n0+tx4..+3, n0+64+tx4..+3}
    float4 bb0 = *(const float4*)(bias + n0 + tx4);
    float4 bb1 = *(const float4*)(bias + n0 + 64 + tx4);
#pragma unroll
    for (int i = 0; i < 8; i++) {
        const int mr = (i < 4) ? (ty4 + i) : (64 + ty4 + i - 4);
        float* base;
        if (QKV) base = g_qkv + (size_t)(m0 + mr) * 768 + n0;
        else     base = OUT + so[mr] + n0;
        float4 o0, o1;
        UNPACK2(o0.x, o0.y, acc[i][0]);
        UNPACK2(o0.z, o0.w, acc[i][1]);
        UNPACK2(o1.x, o1.y, acc[i][2]);
        UNPACK2(o1.z, o1.w, acc[i][3]);
        o0.x += bb0.x; o0.y += bb0.y; o0.z += bb0.z; o0.w += bb0.w;
        o1.x += bb1.x; o1.y += bb1.y; o1.z += bb1.z; o1.w += bb1.w;
        *(float4*)(base + tx4)      = o0;
        *(float4*)(base + 64 + tx4) = o1;
    }
}

// =====================================================================
// Kernel 2: windowed attention. One block per (window, head).
// =====================================================================
__global__ __launch_bounds__(256) void attn_kernel() {
    __shared__ float qs[NN * HD];
    __shared__ float vs[NN * HD];
    __shared__ float kT[HD * 56];
    __shared__ float sS[NN * 52];

    const int w = blockIdx.x >> 3;
    const int h = blockIdx.x & 7;
    const int t = threadIdx.x;

    const int wi = w & 63;
    const int cls = (((wi >> 3) == 7) ? 2 : 0) | (((wi & 7) == 7) ? 1 : 0);
    const float* gb = g_bias + (size_t)((cls * HEADS + h) * NN) * 52;

    const float* base = g_qkv + (size_t)w * NN * 768 + h * HD;
    for (int idx = t; idx < NN * 8; idx += 256) {
        int n = idx >> 3, dq = idx & 7;
        const float4* p = (const float4*)(base + n * 768 + dq * 4);
        float4 q4 = p[0];
        float4 k4 = p[64];
        float4 v4 = p[128];
        *(float4*)&qs[n * HD + dq * 4] = q4;
        *(float4*)&vs[n * HD + dq * 4] = v4;
        kT[(dq * 4 + 0) * 56 + n] = k4.x;
        kT[(dq * 4 + 1) * 56 + n] = k4.y;
        kT[(dq * 4 + 2) * 56 + n] = k4.z;
        kT[(dq * 4 + 3) * 56 + n] = k4.w;
    }
    __syncthreads();

    const int jg = t & 63, rgp = t >> 6;
    const float scale = 0.17677669529663687f;
    for (int i = rgp; i < NN; i += 4) {
        if (jg < NN) {
            float acc = 0.f;
#pragma unroll
            for (int kk = 0; kk < HD; kk++)
                acc += qs[i * HD + kk] * kT[kk * 56 + jg];
            sS[i * 52 + jg] = acc * scale + __ldg(&gb[i * 52 + jg]);
        }
    }
    __syncthreads();

    const int wid = t >> 5, lane = t & 31;
    for (int i = wid; i < NN; i += 8) {
        float e0 = sS[i * 52 + lane];
        float e1 = (lane + 32 < NN) ? sS[i * 52 + lane + 32] : -1e30f;
        float mx = fmaxf(e0, e1);
#pragma unroll
        for (int o = 16; o; o >>= 1) mx = fmaxf(mx, __shfl_xor_sync(0xffffffffu, mx, o));
        e0 = __expf(e0 - mx);
        e1 = (lane + 32 < NN) ? __expf(e1 - mx) : 0.f;
        float sm = e0 + e1;
#pragma unroll
        for (int o = 16; o; o >>= 1) sm += __shfl_xor_sync(0xffffffffu, sm, o);
        float inv = 1.f / sm;
        sS[i * 52 + lane] = e0 * inv;
        if (lane + 32 < NN) sS[i * 52 + lane + 32] = e1 * inv;
    }
    __syncthreads();

    const int d = t & 31, ig = t >> 5;
    float* outp = g_att + (size_t)w * NN * 256 + h * HD + d;
    for (int i = ig; i < NN; i += 8) {
        float acc = 0.f;
#pragma unroll
        for (int j = 0; j < NN; j++)
            acc += sS[i * 52 + j] * vs[j * HD + d];
        outp[i * 256] = acc;
    }
}

// =====================================================================
extern "C" void kernel_launch(void* const* d_in, const int* in_sizes, int n_in,
                              void* d_out, int out_size) {
    const float* x     = (const float*)d_in[0];
    const float* qkvw  = (const float*)d_in[1];
    const float* qkvb  = (const float*)d_in[2];
    const float* projw = (const float*)d_in[3];
    const float* projb = (const float*)d_in[4];
    const float* tbl   = (const float*)d_in[5];
    const int*   ridx  = (const int*)d_in[6];
    float* out = (float*)d_out;

    (void)in_sizes; (void)n_in; (void)out_size;

    cudaFuncSetAttribute(gemm128<true>,  cudaFuncAttributeMaxDynamicSharedMemorySize, GM_SMEM);
    cudaFuncSetAttribute(gemm128<false>, cudaFuncAttributeMaxDynamicSharedMemorySize, GM_SMEM);

    bias_kernel<<<32, 256>>>(tbl, ridx);
    gemm128<true><<<dim3(6, MTOT / 128), 256, GM_SMEM>>>(x, qkvw, qkvb, nullptr);
    attn_kernel<<<NWTOT * HEADS, 256>>>();
    gemm128<false><<<dim3(2, MTOT / 128), 256, GM_SMEM>>>(nullptr, projw, projb, out);
}